// round 5
// baseline (speedup 1.0000x reference)
#include <cuda_runtime.h>
#include <cuda_bf16.h>

#define FDIM 128

// Vector reduction (no return) into global memory.
__device__ __forceinline__ void red_add_v4(float* addr, float4 v) {
    asm volatile("red.global.add.v4.f32 [%0], {%1, %2, %3, %4};"
                 :: "l"(addr), "f"(v.x), "f"(v.y), "f"(v.z), "f"(v.w)
                 : "memory");
}

__device__ __forceinline__ float sigmoidf_fast(float x) {
    return 1.0f / (1.0f + __expf(-x));
}

// One warp processes CHUNK consecutive rows, unrolled by 4 (measured-best MLP).
// Lane l owns features [4l, 4l+4). 32-bit indexing + walked pointer to keep
// register count low. Sorted segments -> register accumulate, flush via
// red.global only at segment boundaries (group fast path when all 4 rows stay).
template <int CHUNK, bool WRITE_LOGITS>
__device__ __forceinline__ void run_side(const float* __restrict__ feats,
                                         const float* __restrict__ W,
                                         const float* __restrict__ bptr,
                                         const int*   __restrict__ seg,
                                         unsigned n_rows,
                                         float* __restrict__ out_sum,
                                         float* __restrict__ out_logits,
                                         unsigned chunk_idx, unsigned lane)
{
    const unsigned row0 = chunk_idx * CHUNK;
    if (row0 >= n_rows) return;
    const unsigned row_end = min(n_rows, row0 + CHUNK);

    const float4 w4  = reinterpret_cast<const float4*>(W)[lane];
    const float bias = __ldg(bptr);

    float4 acc = make_float4(0.f, 0.f, 0.f, 0.f);
    int cur = __ldg(seg + row0);

    // Row r's float4 for this lane lives at index r*32 + lane.
    const float4* fp = reinterpret_cast<const float4*>(feats) + (size_t)row0 * 32u + lane;

    unsigned r = row0;
    for (; r + 3 < row_end; r += 4, fp += 128) {
        const float4 f0 = fp[0];
        const float4 f1 = fp[32];
        const float4 f2 = fp[64];
        const float4 f3 = fp[96];
        const int4  s4  = *reinterpret_cast<const int4*>(seg + r);   // uniform, L1-hit

        float p0 = f0.x * w4.x + f0.y * w4.y + f0.z * w4.z + f0.w * w4.w;
        float p1 = f1.x * w4.x + f1.y * w4.y + f1.z * w4.z + f1.w * w4.w;
        float p2 = f2.x * w4.x + f2.y * w4.y + f2.z * w4.z + f2.w * w4.w;
        float p3 = f3.x * w4.x + f3.y * w4.y + f3.z * w4.z + f3.w * w4.w;

        // 4 interleaved butterfly chains: SHFL latencies overlap across rows.
        #pragma unroll
        for (int o = 16; o > 0; o >>= 1) {
            p0 += __shfl_xor_sync(0xffffffffu, p0, o);
            p1 += __shfl_xor_sync(0xffffffffu, p1, o);
            p2 += __shfl_xor_sync(0xffffffffu, p2, o);
            p3 += __shfl_xor_sync(0xffffffffu, p3, o);
        }
        p0 += bias; p1 += bias; p2 += bias; p3 += bias;

        if (WRITE_LOGITS && lane == 0) {
            // r is a multiple of 4 -> 16B-aligned vector store.
            *reinterpret_cast<float4*>(out_logits + r) = make_float4(p0, p1, p2, p3);
        }

        const float g0 = sigmoidf_fast(p0);
        const float g1 = sigmoidf_fast(p1);
        const float g2 = sigmoidf_fast(p2);
        const float g3 = sigmoidf_fast(p3);

        if (s4.w == cur) {
            // Fast path: whole group in current segment (seg sorted, s >= cur).
            acc.x += g0 * f0.x; acc.y += g0 * f0.y; acc.z += g0 * f0.z; acc.w += g0 * f0.w;
            acc.x += g1 * f1.x; acc.y += g1 * f1.y; acc.z += g1 * f1.z; acc.w += g1 * f1.w;
            acc.x += g2 * f2.x; acc.y += g2 * f2.y; acc.z += g2 * f2.z; acc.w += g2 * f2.w;
            acc.x += g3 * f3.x; acc.y += g3 * f3.y; acc.z += g3 * f3.z; acc.w += g3 * f3.w;
        } else {
            if (s4.x != cur) { red_add_v4(out_sum + (size_t)cur * FDIM + lane * 4, acc);
                               acc = make_float4(0.f,0.f,0.f,0.f); cur = s4.x; }
            acc.x += g0 * f0.x; acc.y += g0 * f0.y; acc.z += g0 * f0.z; acc.w += g0 * f0.w;
            if (s4.y != cur) { red_add_v4(out_sum + (size_t)cur * FDIM + lane * 4, acc);
                               acc = make_float4(0.f,0.f,0.f,0.f); cur = s4.y; }
            acc.x += g1 * f1.x; acc.y += g1 * f1.y; acc.z += g1 * f1.z; acc.w += g1 * f1.w;
            if (s4.z != cur) { red_add_v4(out_sum + (size_t)cur * FDIM + lane * 4, acc);
                               acc = make_float4(0.f,0.f,0.f,0.f); cur = s4.z; }
            acc.x += g2 * f2.x; acc.y += g2 * f2.y; acc.z += g2 * f2.z; acc.w += g2 * f2.w;
            if (s4.w != cur) { red_add_v4(out_sum + (size_t)cur * FDIM + lane * 4, acc);
                               acc = make_float4(0.f,0.f,0.f,0.f); cur = s4.w; }
            acc.x += g3 * f3.x; acc.y += g3 * f3.y; acc.z += g3 * f3.z; acc.w += g3 * f3.w;
        }
    }
    // Scalar tail (not hit for the given shapes, kept for safety).
    for (; r < row_end; ++r, fp += 32) {
        const float4 fv = fp[0];
        float p = fv.x * w4.x + fv.y * w4.y + fv.z * w4.z + fv.w * w4.w;
        #pragma unroll
        for (int o = 16; o > 0; o >>= 1)
            p += __shfl_xor_sync(0xffffffffu, p, o);
        p += bias;
        if (WRITE_LOGITS && lane == 0) out_logits[r] = p;
        const float gv = sigmoidf_fast(p);
        const int sv = __ldg(seg + r);
        if (sv != cur) {
            red_add_v4(out_sum + (size_t)cur * FDIM + lane * 4, acc);
            acc = make_float4(0.f, 0.f, 0.f, 0.f);
            cur = sv;
        }
        acc.x += gv * fv.x; acc.y += gv * fv.y; acc.z += gv * fv.z; acc.w += gv * fv.w;
    }
    red_add_v4(out_sum + (size_t)cur * FDIM + lane * 4, acc);
}

// Persistent grid-stride warps: each warp strides over all chunks (atom side
// first, then vir), eliminating discrete wave tails and the serialized vir tail.
__global__ __launch_bounds__(256, 4)
void fused_gated_segsum(const float* __restrict__ atom_feats,
                        const float* __restrict__ W_atom,
                        const float* __restrict__ b_atom,
                        const int*   __restrict__ atom_seg,
                        unsigned n_atom, unsigned atom_chunks,
                        const float* __restrict__ vir_feats,
                        const float* __restrict__ W_vir,
                        const float* __restrict__ b_vir,
                        const int*   __restrict__ vir_seg,
                        unsigned n_vir, unsigned vir_chunks,
                        float* __restrict__ sum_atom,
                        float* __restrict__ sum_vir,
                        float* __restrict__ logits)
{
    const unsigned lane = threadIdx.x & 31u;
    const unsigned gw   = (blockIdx.x * blockDim.x + threadIdx.x) >> 5;
    const unsigned nw   = (gridDim.x * blockDim.x) >> 5;
    const unsigned total = atom_chunks + vir_chunks;

    for (unsigned c = gw; c < total; c += nw) {
        if (c < atom_chunks) {
            run_side<64, true>(atom_feats, W_atom, b_atom, atom_seg, n_atom,
                               sum_atom, logits, c, lane);
        } else {
            run_side<8, false>(vir_feats, W_vir, b_vir, vir_seg, n_vir,
                               sum_vir, nullptr, c - atom_chunks, lane);
        }
    }
}

extern "C" void kernel_launch(void* const* d_in, const int* in_sizes, int n_in,
                              void* d_out, int out_size) {
    const float* atom_feats = (const float*)d_in[0];
    const float* vir_feats  = (const float*)d_in[1];
    const float* W_atom     = (const float*)d_in[2];
    const float* b_atom     = (const float*)d_in[3];
    const float* W_vir      = (const float*)d_in[4];
    const float* b_vir      = (const float*)d_in[5];
    const int*   atom_seg   = (const int*)d_in[6];
    const int*   vir_seg    = (const int*)d_in[7];

    const unsigned n_atom = (unsigned)(in_sizes[0] / FDIM);
    const unsigned n_vir  = (unsigned)(in_sizes[1] / FDIM);
    const unsigned num_graphs = (unsigned)((out_size - (int)n_atom) / (2 * FDIM));

    float* out      = (float*)d_out;
    float* sum_atom = out;
    float* sum_vir  = out + (size_t)num_graphs * FDIM;
    float* logits   = out + (size_t)num_graphs * FDIM * 2;

    // Zero only the segment-sum regions (logits fully overwritten).
    cudaMemsetAsync(out, 0, (size_t)num_graphs * FDIM * 2 * sizeof(float), 0);

    constexpr unsigned CHUNK_A = 64;
    constexpr unsigned CHUNK_V = 8;
    constexpr int THREADS = 256;   // 8 warps / CTA

    const unsigned atom_chunks = (n_atom + CHUNK_A - 1) / CHUNK_A;
    const unsigned vir_chunks  = (n_vir  + CHUNK_V - 1) / CHUNK_V;
    const unsigned total_warps = atom_chunks + vir_chunks;

    // Persistent grid: 4 CTAs/SM on 152 SMs (GB300); clamp for tiny inputs.
    unsigned blocks = 152u * 4u;
    const unsigned needed = (total_warps + 7u) / 8u;
    if (needed < blocks) blocks = needed;

    fused_gated_segsum<<<blocks, THREADS>>>(
        atom_feats, W_atom, b_atom, atom_seg, n_atom, atom_chunks,
        vir_feats,  W_vir,  b_vir,  vir_seg,  n_vir,  vir_chunks,
        sum_atom, sum_vir, logits);
}